// round 1
// baseline (speedup 1.0000x reference)
#include <cuda_runtime.h>
#include <cstdint>

// Problem constants
#define BATCH      256
#define OUTN       64
#define IN_F       262144      // 4*256*256
#define HALF_S     128
// Tiling
#define BM         64          // batch rows per block
#define QPS        16          // quads per stage
#define KCT        64          // t-values per stage (QPS*4)
#define KB         128         // split-K blocks
#define QPKB       512         // quads per K-block (65536/128)
#define NSTAGES    32          // QPKB/QPS
#define RS         68          // smem row stride in floats (64 + 4 pad, 272B % 16 == 0)
#define NTHREADS   128

// Deterministic split-K scratch: [KB][BATCH][OUTN] = 8 MB
__device__ float g_partial[KB * BATCH * OUTN];

__global__ __launch_bounds__(NTHREADS)
void wl_gemm(const float* __restrict__ x, const float* __restrict__ W)
{
    __shared__ __align__(16) float ts[KCT * RS];   // transformed x tile: [k][row]
    __shared__ __align__(16) float ws[KCT * RS];   // W tile transposed:  [k][out]

    const int tid = threadIdx.x;
    const int mt  = blockIdx.x;          // 0..3   M tile
    const int kb  = blockIdx.y;          // 0..127 K block
    const int rowbase = mt * BM;

    const int o0 = (tid & 15) * 4;       // this thread's 4 outputs
    const int r0 = (tid >> 4) * 8;       // this thread's 8 rows

    float acc[8][4];
#pragma unroll
    for (int i = 0; i < 8; ++i)
#pragma unroll
        for (int j = 0; j < 4; ++j) acc[i][j] = 0.0f;

    // x-loader mapping (per stage): 64 rows x 8 float4-pair positions
    const int cpos  = tid & 7;           // 0..7 : float4 position along columns
    const int brow0 = tid >> 3;          // 0..15

    for (int s = 0; s < NSTAGES; ++s) {
        const int qbase = kb * QPKB + s * QPS;     // quad base index
        const int ch  = qbase >> 14;               // /16384
        const int r2  = (qbase >> 7) & 127;
        const int c0  = qbase & 127;               // multiple of 16

        // ---- load x quads, apply Haar butterfly, store t to smem [k][row] ----
#pragma unroll
        for (int it = 0; it < 4; ++it) {
            const int br = brow0 + it * 16;
            const float* xr = x + (size_t)(rowbase + br) * IN_F
                                + ch * 65536 + (2 * r2) * 256 + 2 * c0 + cpos * 4;
            const float4 tp = *(const float4*)xr;          // (a0,b0,a1,b1)  even row
            const float4 bt = *(const float4*)(xr + 256);  // (c0,d0,c1,d1)  odd row

            // quad 0
            {
                const float apb = tp.x + tp.y, amb = tp.x - tp.y;
                const float cpd = bt.x + bt.y, cmd = bt.x - bt.y;
                const int c2l = cpos * 2;
                ts[(0 * QPS + c2l) * RS + br] = (apb + cpd) * 0.5f;  // LL
                ts[(1 * QPS + c2l) * RS + br] = (apb - cpd) * 0.5f;  // LH
                ts[(2 * QPS + c2l) * RS + br] = (amb + cmd) * 0.5f;  // HL
                ts[(3 * QPS + c2l) * RS + br] = (amb - cmd) * 0.5f;  // HH
            }
            // quad 1
            {
                const float apb = tp.z + tp.w, amb = tp.z - tp.w;
                const float cpd = bt.z + bt.w, cmd = bt.z - bt.w;
                const int c2l = cpos * 2 + 1;
                ts[(0 * QPS + c2l) * RS + br] = (apb + cpd) * 0.5f;
                ts[(1 * QPS + c2l) * RS + br] = (apb - cpd) * 0.5f;
                ts[(2 * QPS + c2l) * RS + br] = (amb + cmd) * 0.5f;
                ts[(3 * QPS + c2l) * RS + br] = (amb - cmd) * 0.5f;
            }
        }

        // ---- load W tile (natural t-index layout), transpose into smem [k][out] ----
        // 64 k * 64 out = 1024 float4 units
#pragma unroll
        for (int it = 0; it < 8; ++it) {
            const int u   = it * 128 + tid;
            const int o   = u >> 4;           // 0..63
            const int f4  = u & 15;
            const int sub = f4 >> 2;          // 0..3
            const int c4  = (f4 & 3) * 4;     // 0,4,8,12
            const float4 wv = *(const float4*)(W + (size_t)o * IN_F
                                + ((size_t)(ch * 4 + sub) * HALF_S + r2) * HALF_S + c0 + c4);
            const int kk = sub * QPS + c4;
            ws[(kk + 0) * RS + o] = wv.x;
            ws[(kk + 1) * RS + o] = wv.y;
            ws[(kk + 2) * RS + o] = wv.z;
            ws[(kk + 3) * RS + o] = wv.w;
        }

        __syncthreads();

        // ---- register-tile outer product ----
#pragma unroll 4
        for (int k = 0; k < KCT; ++k) {
            const float4 wv = *(const float4*)&ws[k * RS + o0];
            const float4 xa = *(const float4*)&ts[k * RS + r0];
            const float4 xb = *(const float4*)&ts[k * RS + r0 + 4];
            const float xv[8] = {xa.x, xa.y, xa.z, xa.w, xb.x, xb.y, xb.z, xb.w};
            const float wr[4] = {wv.x, wv.y, wv.z, wv.w};
#pragma unroll
            for (int i = 0; i < 8; ++i)
#pragma unroll
                for (int j = 0; j < 4; ++j)
                    acc[i][j] = fmaf(xv[i], wr[j], acc[i][j]);
        }

        __syncthreads();
    }

    // ---- write partial tile (plain stores, deterministic) ----
    float* pp = g_partial + (size_t)kb * (BATCH * OUTN);
#pragma unroll
    for (int i = 0; i < 8; ++i) {
        float4 v = make_float4(acc[i][0], acc[i][1], acc[i][2], acc[i][3]);
        *(float4*)&pp[(rowbase + r0 + i) * OUTN + o0] = v;
    }
}

__global__ __launch_bounds__(256)
void wl_reduce(const float* __restrict__ bias, float* __restrict__ out)
{
    const int i = blockIdx.x * blockDim.x + threadIdx.x;   // 0..16383
    float ssum = bias[i & (OUTN - 1)];
#pragma unroll 8
    for (int kbi = 0; kbi < KB; ++kbi)
        ssum += g_partial[kbi * (BATCH * OUTN) + i];
    out[i] = ssum;
}

extern "C" void kernel_launch(void* const* d_in, const int* in_sizes, int n_in,
                              void* d_out, int out_size)
{
    const float* x  = (const float*)d_in[0];   // [256, 262144]
    const float* W  = (const float*)d_in[1];   // [64, 262144]
    const float* bb = (const float*)d_in[2];   // [64]
    float* out = (float*)d_out;                // [256, 64]

    dim3 grid(4, KB);          // x-major: 4 M-tiles sharing a W slice run adjacently (L2 reuse)
    wl_gemm<<<grid, NTHREADS>>>(x, W);
    wl_reduce<<<(BATCH * OUTN) / 256, 256>>>(bb, out);
}

// round 5
// speedup vs baseline: 2.1173x; 2.1173x over previous
#include <cuda_runtime.h>
#include <cstdint>

// Problem constants
#define BATCH      256
#define OUTN       64
#define IN_F       262144      // 4*256*256
// Tiling
#define BM         64          // batch rows per block
#define KB         128         // split-K blocks
#define QPKB       512         // quads per K-block
#define QPS        16          // quads per stage
#define NSTAGES    32
#define RSK        68          // smem k-stride (64 + 4 pad) -> conflict-free mma frags
#define NTHREADS   128

// Deterministic split-K scratch
__device__ float g_partial[KB * BATCH * OUTN];   // 8 MB
__device__ float g_p2[8 * BATCH * OUTN];         // 512 KB

__device__ __forceinline__ unsigned f2tf(float f) {
    unsigned u; asm("cvt.rna.tf32.f32 %0, %1;" : "=r"(u) : "f"(f)); return u;
}

__global__ __launch_bounds__(NTHREADS, 6)
void wl_gemm(const float* __restrict__ x, const float* __restrict__ W)
{
    __shared__ __align__(16) float ts[BM * RSK];    // t tile  [row][k]
    __shared__ __align__(16) float ws[OUTN * RSK];  // W tile  [out][k] (natural layout)

    const int tid  = threadIdx.x;
    const int lane = tid & 31;
    const int warp = tid >> 5;
    const int mt   = blockIdx.x;       // 0..3
    const int kb   = blockIdx.y;       // 0..127
    const int rowbase = mt * BM;

    const int g  = lane >> 2;          // mma groupID
    const int t4 = lane & 3;           // mma thread-in-group
    const int mrow0 = (warp & 1) * 32; // warp's 32-row slice
    const int ncol0 = (warp >> 1) * 32;// warp's 32-out slice

    const int cpos  = tid & 7;         // x loader: float4 position
    const int brow0 = tid >> 3;        // x loader: row group

    float acc[2][4][4];
#pragma unroll
    for (int m = 0; m < 2; ++m)
#pragma unroll
        for (int n = 0; n < 4; ++n)
#pragma unroll
            for (int j = 0; j < 4; ++j) acc[m][n][j] = 0.0f;

    for (int s = 0; s < NSTAGES; ++s) {
        const int qb = kb * QPKB + s * QPS;
        const int ch = qb >> 14;
        const int r2 = (qb >> 7) & 127;
        const int c0 = qb & 127;

        // ---- W tile via cp.async, natural [out][k] layout, k = band*16 + cq ----
        {
            const size_t wbase = (size_t)(ch * 4) * 16384 + (size_t)r2 * 128 + c0;
#pragma unroll
            for (int it = 0; it < 8; ++it) {
                const int u    = it * 128 + tid;
                const int o    = u >> 4;
                const int f4   = u & 15;
                const int band = f4 >> 2;
                const int c4   = (f4 & 3) * 4;
                const float* src = W + (size_t)o * IN_F + wbase + band * 16384 + c4;
                const unsigned dst =
                    (unsigned)__cvta_generic_to_shared(&ws[o * RSK + band * 16 + c4]);
                asm volatile("cp.async.cg.shared.global [%0], [%1], 16;\n"
                             :: "r"(dst), "l"(src));
            }
            asm volatile("cp.async.commit_group;\n");
        }

        // ---- x load (streaming) + Haar butterfly -> ts [row][k] ----
#pragma unroll
        for (int it = 0; it < 4; ++it) {
            const int br = brow0 + it * 16;
            const float* xr = x + (size_t)(rowbase + br) * IN_F
                                + ch * 65536 + (2 * r2) * 256 + 2 * c0 + cpos * 4;
            const float4 tp = __ldcs((const float4*)xr);          // a0,b0,a1,b1
            const float4 bt = __ldcs((const float4*)(xr + 256));  // c0,d0,c1,d1

            const float apb0 = tp.x + tp.y, amb0 = tp.x - tp.y;
            const float cpd0 = bt.x + bt.y, cmd0 = bt.x - bt.y;
            const float apb1 = tp.z + tp.w, amb1 = tp.z - tp.w;
            const float cpd1 = bt.z + bt.w, cmd1 = bt.z - bt.w;

            float* tr = &ts[br * RSK + 2 * cpos];
            *(float2*)(tr +  0) = make_float2((apb0 + cpd0) * 0.5f, (apb1 + cpd1) * 0.5f); // LL
            *(float2*)(tr + 16) = make_float2((apb0 - cpd0) * 0.5f, (apb1 - cpd1) * 0.5f); // LH
            *(float2*)(tr + 32) = make_float2((amb0 + cmd0) * 0.5f, (amb1 + cmd1) * 0.5f); // HL
            *(float2*)(tr + 48) = make_float2((amb0 - cmd0) * 0.5f, (amb1 - cmd1) * 0.5f); // HH
        }

        asm volatile("cp.async.wait_group 0;\n");
        __syncthreads();

        // ---- tf32 mma: warp tile 32 rows x 32 outs ----
#pragma unroll
        for (int ks = 0; ks < 8; ++ks) {
            const int k0 = ks * 8;
            unsigned a[2][4];
#pragma unroll
            for (int m = 0; m < 2; ++m) {
                const int rm = mrow0 + m * 16;
                a[m][0] = f2tf(ts[(rm + g    ) * RSK + k0     + t4]);
                a[m][1] = f2tf(ts[(rm + 8 + g) * RSK + k0     + t4]);
                a[m][2] = f2tf(ts[(rm + g    ) * RSK + k0 + 4 + t4]);
                a[m][3] = f2tf(ts[(rm + 8 + g) * RSK + k0 + 4 + t4]);
            }
#pragma unroll
            for (int n = 0; n < 4; ++n) {
                const int nc = ncol0 + n * 8;
                const unsigned b0 = f2tf(ws[(nc + g) * RSK + k0     + t4]);
                const unsigned b1 = f2tf(ws[(nc + g) * RSK + k0 + 4 + t4]);
#pragma unroll
                for (int m = 0; m < 2; ++m) {
                    asm volatile(
                        "mma.sync.aligned.m16n8k8.row.col.f32.tf32.tf32.f32 "
                        "{%0,%1,%2,%3}, {%4,%5,%6,%7}, {%8,%9}, {%0,%1,%2,%3};\n"
                        : "+f"(acc[m][n][0]), "+f"(acc[m][n][1]),
                          "+f"(acc[m][n][2]), "+f"(acc[m][n][3])
                        : "r"(a[m][0]), "r"(a[m][1]), "r"(a[m][2]), "r"(a[m][3]),
                          "r"(b0), "r"(b1));
                }
            }
        }
        __syncthreads();
    }

    // ---- write split-K partial tile ----
    float* pp = g_partial + (size_t)kb * (BATCH * OUTN);
#pragma unroll
    for (int m = 0; m < 2; ++m)
#pragma unroll
        for (int n = 0; n < 4; ++n) {
            const int r = rowbase + mrow0 + m * 16 + g;
            const int c = ncol0 + n * 8 + 2 * t4;
            *(float2*)&pp[r * OUTN + c]       = make_float2(acc[m][n][0], acc[m][n][1]);
            *(float2*)&pp[(r + 8) * OUTN + c] = make_float2(acc[m][n][2], acc[m][n][3]);
        }
}

// Stage 1: 8 groups of 16 kb-slices each. grid 512x256, fully parallel, coalesced.
__global__ __launch_bounds__(256)
void wl_reduce1()
{
    const int idx = blockIdx.x * 256 + threadIdx.x;   // 0..131071
    const int e   = idx & (BATCH * OUTN - 1);
    const int grp = idx >> 14;
    const float* p = g_partial + (size_t)(grp * 16) * (BATCH * OUTN) + e;
    float ssum = 0.0f;
#pragma unroll
    for (int j = 0; j < 16; ++j)
        ssum += p[(size_t)j * (BATCH * OUTN)];
    g_p2[idx] = ssum;
}

// Stage 2: fold 8 groups + bias.
__global__ __launch_bounds__(256)
void wl_reduce2(const float* __restrict__ bias, float* __restrict__ out)
{
    const int e = blockIdx.x * 256 + threadIdx.x;     // 0..16383
    float ssum = bias[e & (OUTN - 1)];
#pragma unroll
    for (int gi = 0; gi < 8; ++gi)
        ssum += g_p2[gi * (BATCH * OUTN) + e];
    out[e] = ssum;
}

extern "C" void kernel_launch(void* const* d_in, const int* in_sizes, int n_in,
                              void* d_out, int out_size)
{
    const float* x  = (const float*)d_in[0];   // [256, 262144]
    const float* W  = (const float*)d_in[1];   // [64, 262144]
    const float* bb = (const float*)d_in[2];   // [64]
    float* out = (float*)d_out;                // [256, 64]

    dim3 grid(4, KB);   // x-major: the 4 M-tiles sharing a W slice are co-resident (L2 reuse)
    wl_gemm<<<grid, NTHREADS>>>(x, W);
    wl_reduce1<<<512, 256>>>();
    wl_reduce2<<<64, 256>>>(bb, out);
}

// round 6
// speedup vs baseline: 2.8786x; 1.3596x over previous
#include <cuda_runtime.h>
#include <cstdint>

// Problem constants
#define BATCH      256
#define OUTN       64
#define IN_F       262144      // 4*256*256
// Tiling
#define BM         64          // batch rows per block
#define KB         256         // split-K blocks
#define QPKB       256         // quads per K-block (65536/256)
#define QPS        16          // quads per stage
#define NSTAGES    16          // QPKB/QPS
#define RSK        68          // smem k-stride (64+4 pad): conflict-free mma frags
#define NTHREADS   128
#define TS_FLOATS  (BM * RSK)      // 4352
#define WS_FLOATS  (OUTN * RSK)    // 4352
#define SMEM_BYTES ((TS_FLOATS + 2 * WS_FLOATS) * 4)   // 52224

// Deterministic split-K scratch
__device__ float g_partial[KB * BATCH * OUTN];   // 16 MB
__device__ float g_p2[8 * BATCH * OUTN];         // 512 KB

__device__ __forceinline__ unsigned f2tf(float f) {
    unsigned u; asm("cvt.rna.tf32.f32 %0, %1;" : "=r"(u) : "f"(f)); return u;
}

__global__ __launch_bounds__(NTHREADS, 4)
void wl_gemm(const float* __restrict__ x, const float* __restrict__ W)
{
    extern __shared__ __align__(16) float smem[];
    float* ts = smem;                  // t tile [row][k]
    float* ws = smem + TS_FLOATS;      // W tiles [2][out][k]

    const int tid  = threadIdx.x;
    const int lane = tid & 31;
    const int warp = tid >> 5;
    const int mt   = blockIdx.x;       // 0..3
    const int kb   = blockIdx.y;       // 0..255
    const int rowbase = mt * BM;

    const int g  = lane >> 2;          // mma groupID
    const int t4 = lane & 3;           // mma thread-in-group
    const int mrow0 = (warp & 1) * 32;
    const int ncol0 = (warp >> 1) * 32;

    const int cpos  = tid & 7;         // x loader: float4 position
    const int brow0 = tid >> 3;        // x loader: row group

    float acc[2][4][4];
#pragma unroll
    for (int m = 0; m < 2; ++m)
#pragma unroll
        for (int n = 0; n < 4; ++n)
#pragma unroll
            for (int j = 0; j < 4; ++j) acc[m][n][j] = 0.0f;

    float4 tp[4], bt[4];               // x prefetch registers (one stage)

    // ---------------- helpers (macros keep everything in registers) ----------
#define STAGE_COORDS(s, ch, r2, c0)                       \
    const int qb_##s = kb * QPKB + (s) * QPS;             \
    const int ch = qb_##s >> 14;                          \
    const int r2 = (qb_##s >> 7) & 127;                   \
    const int c0 = qb_##s & 127;

#define PREFETCH_X(ch, r2, c0)                                                  \
    _Pragma("unroll")                                                           \
    for (int it = 0; it < 4; ++it) {                                            \
        const int br = brow0 + it * 16;                                         \
        const float* xr = x + (size_t)(rowbase + br) * IN_F                     \
                            + ch * 65536 + (2 * r2) * 256 + 2 * c0 + cpos * 4;  \
        tp[it] = __ldcs((const float4*)xr);                                     \
        bt[it] = __ldcs((const float4*)(xr + 256));                             \
    }

#define CP_W(ch, r2, c0, buf)                                                   \
    {                                                                           \
        const size_t wbase = (size_t)(ch * 4) * 16384 + (size_t)r2 * 128 + c0;  \
        float* wbuf = ws + (buf) * WS_FLOATS;                                   \
        _Pragma("unroll")                                                       \
        for (int it = 0; it < 8; ++it) {                                        \
            const int u    = it * 128 + tid;                                    \
            const int o    = u >> 4;                                            \
            const int f4   = u & 15;                                            \
            const int band = f4 >> 2;                                           \
            const int c4   = (f4 & 3) * 4;                                      \
            const float* src = W + (size_t)o * IN_F + wbase + band * 16384 + c4;\
            const unsigned dst =                                                \
                (unsigned)__cvta_generic_to_shared(&wbuf[o * RSK + band * 16 + c4]); \
            asm volatile("cp.async.cg.shared.global [%0], [%1], 16;\n"          \
                         :: "r"(dst), "l"(src));                                \
        }                                                                       \
        asm volatile("cp.async.commit_group;\n");                              \
    }

    // ---------------- prologue ----------------
    {
        STAGE_COORDS(0, ch0, r20, c00);
        PREFETCH_X(ch0, r20, c00);
        CP_W(ch0, r20, c00, 0);
    }

    for (int s = 0; s < NSTAGES; ++s) {
        __syncthreads();               // mma(s-1) finished reading ts

        // ---- butterfly current x regs -> ts [row][k] ----
#pragma unroll
        for (int it = 0; it < 4; ++it) {
            const int br = brow0 + it * 16;
            const float apb0 = tp[it].x + tp[it].y, amb0 = tp[it].x - tp[it].y;
            const float cpd0 = bt[it].x + bt[it].y, cmd0 = bt[it].x - bt[it].y;
            const float apb1 = tp[it].z + tp[it].w, amb1 = tp[it].z - tp[it].w;
            const float cpd1 = bt[it].z + bt[it].w, cmd1 = bt[it].z - bt[it].w;

            float* tr = &ts[br * RSK + 2 * cpos];
            *(float2*)(tr +  0) = make_float2((apb0 + cpd0) * 0.5f, (apb1 + cpd1) * 0.5f); // LL
            *(float2*)(tr + 16) = make_float2((apb0 - cpd0) * 0.5f, (apb1 - cpd1) * 0.5f); // LH
            *(float2*)(tr + 32) = make_float2((amb0 + cmd0) * 0.5f, (amb1 + cmd1) * 0.5f); // HL
            *(float2*)(tr + 48) = make_float2((amb0 - cmd0) * 0.5f, (amb1 - cmd1) * 0.5f); // HH
        }

        // ---- prefetch next stage (x regs + W cp.async) ----
        if (s + 1 < NSTAGES) {
            const int sn = s + 1;
            const int qbn = kb * QPKB + sn * QPS;
            const int chn = qbn >> 14;
            const int r2n = (qbn >> 7) & 127;
            const int c0n = qbn & 127;
            PREFETCH_X(chn, r2n, c0n);
            CP_W(chn, r2n, c0n, sn & 1);
            asm volatile("cp.async.wait_group 1;\n");   // W(s) arrived, W(s+1) in flight
        } else {
            asm volatile("cp.async.wait_group 0;\n");
        }

        __syncthreads();               // ts + W(s) visible

        // ---- tf32 mma: warp tile 32 rows x 32 outs ----
        const float* wbuf = ws + (s & 1) * WS_FLOATS;
#pragma unroll
        for (int ks = 0; ks < 8; ++ks) {
            const int k0 = ks * 8;
            unsigned a[2][4];
#pragma unroll
            for (int m = 0; m < 2; ++m) {
                const int rm = mrow0 + m * 16;
                a[m][0] = f2tf(ts[(rm + g    ) * RSK + k0     + t4]);
                a[m][1] = f2tf(ts[(rm + 8 + g) * RSK + k0     + t4]);
                a[m][2] = f2tf(ts[(rm + g    ) * RSK + k0 + 4 + t4]);
                a[m][3] = f2tf(ts[(rm + 8 + g) * RSK + k0 + 4 + t4]);
            }
#pragma unroll
            for (int n = 0; n < 4; ++n) {
                const int nc = ncol0 + n * 8;
                const unsigned b0 = f2tf(wbuf[(nc + g) * RSK + k0     + t4]);
                const unsigned b1 = f2tf(wbuf[(nc + g) * RSK + k0 + 4 + t4]);
#pragma unroll
                for (int m = 0; m < 2; ++m) {
                    asm volatile(
                        "mma.sync.aligned.m16n8k8.row.col.f32.tf32.tf32.f32 "
                        "{%0,%1,%2,%3}, {%4,%5,%6,%7}, {%8,%9}, {%0,%1,%2,%3};\n"
                        : "+f"(acc[m][n][0]), "+f"(acc[m][n][1]),
                          "+f"(acc[m][n][2]), "+f"(acc[m][n][3])
                        : "r"(a[m][0]), "r"(a[m][1]), "r"(a[m][2]), "r"(a[m][3]),
                          "r"(b0), "r"(b1));
                }
            }
        }
    }

    // ---- write split-K partial tile ----
    float* pp = g_partial + (size_t)kb * (BATCH * OUTN);
#pragma unroll
    for (int m = 0; m < 2; ++m)
#pragma unroll
        for (int n = 0; n < 4; ++n) {
            const int r = rowbase + mrow0 + m * 16 + g;
            const int c = ncol0 + n * 8 + 2 * t4;
            *(float2*)&pp[r * OUTN + c]       = make_float2(acc[m][n][0], acc[m][n][1]);
            *(float2*)&pp[(r + 8) * OUTN + c] = make_float2(acc[m][n][2], acc[m][n][3]);
        }
}

// Stage 1: 8 groups of 32 kb-slices each. Fully parallel, coalesced.
__global__ __launch_bounds__(256)
void wl_reduce1()
{
    const int idx = blockIdx.x * 256 + threadIdx.x;   // 0..131071
    const int e   = idx & (BATCH * OUTN - 1);
    const int grp = idx >> 14;                         // 0..7
    const float* p = g_partial + (size_t)(grp * 32) * (BATCH * OUTN) + e;
    float ssum = 0.0f;
#pragma unroll
    for (int j = 0; j < 32; ++j)
        ssum += p[(size_t)j * (BATCH * OUTN)];
    g_p2[idx] = ssum;
}

// Stage 2: fold 8 groups + bias.
__global__ __launch_bounds__(256)
void wl_reduce2(const float* __restrict__ bias, float* __restrict__ out)
{
    const int e = blockIdx.x * 256 + threadIdx.x;     // 0..16383
    float ssum = bias[e & (OUTN - 1)];
#pragma unroll
    for (int gi = 0; gi < 8; ++gi)
        ssum += g_p2[gi * (BATCH * OUTN) + e];
    out[e] = ssum;
}

extern "C" void kernel_launch(void* const* d_in, const int* in_sizes, int n_in,
                              void* d_out, int out_size)
{
    const float* x  = (const float*)d_in[0];   // [256, 262144]
    const float* W  = (const float*)d_in[1];   // [64, 262144]
    const float* bb = (const float*)d_in[2];   // [64]
    float* out = (float*)d_out;                // [256, 64]

    // Host-side attribute set (no allocation; capture-safe)
    cudaFuncSetAttribute(wl_gemm, cudaFuncAttributeMaxDynamicSharedMemorySize,
                         SMEM_BYTES);

    dim3 grid(4, KB);   // x-major: the 4 M-tiles sharing a W slice are co-resident (L2 reuse)
    wl_gemm<<<grid, NTHREADS, SMEM_BYTES>>>(x, W);
    wl_reduce1<<<512, 256>>>();
    wl_reduce2<<<64, 256>>>(bb, out);
}